// round 1
// baseline (speedup 1.0000x reference)
#include <cuda_runtime.h>
#include <math.h>
#include <stdint.h>

#define D_DIM 1024
#define H_DIM 2048
#define E_NUM 8
#define CAP   8192
#define N_TOK 8192
#define BM 128
#define BN 128
#define BK 32

// ---------------- device scratch (no allocations allowed) ----------------
__device__ int   g_cnt[E_NUM];
__device__ int   g_off[E_NUM];
__device__ int   g_tok[E_NUM * CAP];
__device__ float g_gate[E_NUM * CAP];
__device__ int   g_inv[N_TOK * 2];
__device__ float g_imp[E_NUM];
__device__ float g_ent;
__device__ float g_h[(size_t)N_TOK * 2 * H_DIM];   // 16384 x 2048 (compact rows)
__device__ float g_y[(size_t)N_TOK * 2 * D_DIM];   // 16384 x 1024 (compact rows)

// ---------------- helpers ----------------
__device__ __forceinline__ unsigned f2tf(float x) {
    unsigned u;
    asm("cvt.rna.tf32.f32 %0, %1;" : "=r"(u) : "f"(x));
    return u;
}

__device__ __forceinline__ void mma_tf32(float* c, const unsigned* a, const unsigned* b) {
    asm volatile(
        "mma.sync.aligned.m16n8k8.row.col.f32.tf32.tf32.f32 "
        "{%0,%1,%2,%3}, {%4,%5,%6,%7}, {%8,%9}, {%0,%1,%2,%3};\n"
        : "+f"(c[0]), "+f"(c[1]), "+f"(c[2]), "+f"(c[3])
        : "r"(a[0]), "r"(a[1]), "r"(a[2]), "r"(a[3]),
          "r"(b[0]), "r"(b[1]));
}

__device__ __forceinline__ float gelu_exact(float v) {
    return 0.5f * v * (1.0f + erff(v * 0.70710678118654752440f));
}

// ---------------- kernels ----------------
__global__ void reset_k() {
    int t = threadIdx.x;
    if (t < E_NUM) { g_cnt[t] = 0; g_imp[t] = 0.0f; }
    if (t == 0)    g_ent = 0.0f;
}

__global__ void router_k(const float* __restrict__ x,
                         const float* __restrict__ gW,
                         const float* __restrict__ gb) {
    int token = (blockIdx.x * blockDim.x + threadIdx.x) >> 5;
    int lane  = threadIdx.x & 31;
    if (token >= N_TOK) return;
    const float* xr = x + (size_t)token * D_DIM;

    float acc[8] = {0.f,0.f,0.f,0.f,0.f,0.f,0.f,0.f};
    for (int d = lane; d < D_DIM; d += 32) {
        float xv = xr[d];
        const float4* w = reinterpret_cast<const float4*>(gW + (size_t)d * E_NUM);
        float4 w0 = w[0], w1 = w[1];
        acc[0] += xv * w0.x; acc[1] += xv * w0.y; acc[2] += xv * w0.z; acc[3] += xv * w0.w;
        acc[4] += xv * w1.x; acc[5] += xv * w1.y; acc[6] += xv * w1.z; acc[7] += xv * w1.w;
    }
#pragma unroll
    for (int e = 0; e < 8; e++)
#pragma unroll
        for (int o = 16; o; o >>= 1) acc[e] += __shfl_xor_sync(0xffffffffu, acc[e], o);
    if (lane) return;

    float lg[8];
#pragma unroll
    for (int e = 0; e < 8; e++) lg[e] = acc[e] + gb[e];

    float mx = lg[0];
#pragma unroll
    for (int e = 1; e < 8; e++) mx = fmaxf(mx, lg[e]);
    float p[8], Z = 0.f;
#pragma unroll
    for (int e = 0; e < 8; e++) { p[e] = expf(lg[e] - mx); Z += p[e]; }
    float ent = 0.f;
#pragma unroll
    for (int e = 0; e < 8; e++) {
        p[e] /= Z;
        ent -= p[e] * logf(p[e] + 1e-8f);
        atomicAdd(&g_imp[e], p[e]);
    }
    atomicAdd(&g_ent, ent);

    int e0 = 0;
#pragma unroll
    for (int e = 1; e < 8; e++) if (lg[e] > lg[e0]) e0 = e;
    int e1 = -1;
#pragma unroll
    for (int e = 0; e < 8; e++) if (e != e0 && (e1 < 0 || lg[e] > lg[e1])) e1 = e;

    float dlt = expf(lg[e1] - lg[e0]);
    float g0 = 1.0f / (1.0f + dlt);
    float g1 = dlt / (1.0f + dlt);

    int s0 = atomicAdd(&g_cnt[e0], 1);
    g_tok[e0 * CAP + s0] = token; g_gate[e0 * CAP + s0] = g0;
    int s1 = atomicAdd(&g_cnt[e1], 1);
    g_tok[e1 * CAP + s1] = token; g_gate[e1 * CAP + s1] = g1;
    g_inv[token * 2 + 0] = e0 * CAP + s0;
    g_inv[token * 2 + 1] = e1 * CAP + s1;
}

// prefix offsets + tail outputs (balance, entropy, util, load[8], importance[8])
__global__ void tail_k(float* __restrict__ out_tail) {
    if (threadIdx.x != 0 || blockIdx.x != 0) return;
    int off = 0;
    float loadv[8], impv[8];
    for (int e = 0; e < 8; e++) { g_off[e] = off; off += g_cnt[e]; }
    for (int e = 0; e < 8; e++) {
        loadv[e] = (float)g_cnt[e] / (float)N_TOK;
        impv[e]  = g_imp[e] / (float)N_TOK;
    }
    float bal = 0.f, util = 0.f;
    for (int e = 0; e < 8; e++) bal += impv[e] * loadv[e];
    bal *= (float)E_NUM;
    for (int e = 0; e < 8; e++) util -= loadv[e] * logf(loadv[e] + 1e-8f);
    out_tail[0] = bal;
    out_tail[1] = g_ent / (float)N_TOK;
    out_tail[2] = util;
    for (int e = 0; e < 8; e++) out_tail[3 + e]  = loadv[e];
    for (int e = 0; e < 8; e++) out_tail[11 + e] = impv[e];
}

// Grouped GEMM. MODE 0: A = gather(x) [K=D], B = W1[e], epilogue gelu -> g_h
//               MODE 1: A = g_h       [K=H], B = W2[e], epilogue +bias -> g_y
template <int MODE>
__global__ void __launch_bounds__(256, 2)
gemm_k(const float* __restrict__ Asrc, const float* __restrict__ Bsrc,
       const float* __restrict__ bias, int Kdim, int Ncols) {
    int e = blockIdx.z;
    int cnt = g_cnt[e];
    int m_base = blockIdx.y * BM;
    if (m_base >= cnt) return;
    int n_base = blockIdx.x * BN;
    int hoff = g_off[e];

    __shared__ float As[BK][BM + 8];
    __shared__ float Bs[BK][BN + 8];

    int tid = threadIdx.x;

    // A load assignment: thread -> (row, 16-col half)
    int arow  = tid >> 1;
    int acol0 = (tid & 1) * 16;
    int m = m_base + arow;
    const float* arow_ptr = nullptr;
    if (m < cnt) {
        size_t row = (MODE == 0) ? (size_t)g_tok[e * CAP + m] : (size_t)(hoff + m);
        const float* base = (MODE == 0) ? Asrc : (const float*)g_h;
        arow_ptr = base + row * (size_t)Kdim;
    }
    // B load assignment
    int brow  = tid >> 3;
    int bcol0 = (tid & 7) * 16;
    const float* Bexp = Bsrc + (size_t)e * Kdim * Ncols;

    int wid = tid >> 5, lane = tid & 31;
    int g = lane >> 2, tig = lane & 3;
    int wm = (wid & 1) * 64;
    int wn = (wid >> 1) * 32;

    float c[4][4][4];
#pragma unroll
    for (int i = 0; i < 4; i++)
#pragma unroll
        for (int j = 0; j < 4; j++)
#pragma unroll
            for (int r = 0; r < 4; r++) c[i][j][r] = 0.f;

    for (int kb = 0; kb < Kdim; kb += BK) {
        if (arow_ptr) {
            const float4* ap = reinterpret_cast<const float4*>(arow_ptr + kb + acol0);
#pragma unroll
            for (int v = 0; v < 4; v++) {
                float4 t = ap[v];
                int kk = acol0 + v * 4;
                As[kk + 0][arow] = __uint_as_float(f2tf(t.x));
                As[kk + 1][arow] = __uint_as_float(f2tf(t.y));
                As[kk + 2][arow] = __uint_as_float(f2tf(t.z));
                As[kk + 3][arow] = __uint_as_float(f2tf(t.w));
            }
        }
        {
            const float4* bp = reinterpret_cast<const float4*>(
                Bexp + (size_t)(kb + brow) * Ncols + n_base + bcol0);
#pragma unroll
            for (int v = 0; v < 4; v++) {
                float4 t = bp[v];
                float4 o;
                o.x = __uint_as_float(f2tf(t.x));
                o.y = __uint_as_float(f2tf(t.y));
                o.z = __uint_as_float(f2tf(t.z));
                o.w = __uint_as_float(f2tf(t.w));
                *reinterpret_cast<float4*>(&Bs[brow][bcol0 + v * 4]) = o;
            }
        }
        __syncthreads();

#pragma unroll
        for (int ks = 0; ks < BK / 8; ks++) {
            int k0 = ks * 8;
            unsigned a[4][4], b[4][2];
#pragma unroll
            for (int i = 0; i < 4; i++) {
                int r = wm + i * 16 + g;
                a[i][0] = __float_as_uint(As[k0 + tig][r]);
                a[i][1] = __float_as_uint(As[k0 + tig][r + 8]);
                a[i][2] = __float_as_uint(As[k0 + tig + 4][r]);
                a[i][3] = __float_as_uint(As[k0 + tig + 4][r + 8]);
            }
#pragma unroll
            for (int j = 0; j < 4; j++) {
                int cc = wn + j * 8 + g;
                b[j][0] = __float_as_uint(Bs[k0 + tig][cc]);
                b[j][1] = __float_as_uint(Bs[k0 + tig + 4][cc]);
            }
#pragma unroll
            for (int i = 0; i < 4; i++)
#pragma unroll
                for (int j = 0; j < 4; j++) mma_tf32(c[i][j], a[i], b[j]);
        }
        __syncthreads();
    }

    // epilogue
    const float* be = bias + (size_t)e * Ncols + n_base;
#pragma unroll
    for (int i = 0; i < 4; i++) {
#pragma unroll
        for (int half = 0; half < 2; half++) {
            int lr = wm + i * 16 + g + half * 8;
            int mrow = m_base + lr;
            if (mrow >= cnt) continue;
            if (MODE == 0) {
                float* hp = g_h + (size_t)(hoff + mrow) * H_DIM + n_base;
#pragma unroll
                for (int j = 0; j < 4; j++) {
                    int col = wn + j * 8 + tig * 2;
                    float v0 = c[i][j][half * 2 + 0] + be[col];
                    float v1 = c[i][j][half * 2 + 1] + be[col + 1];
                    float2 st = make_float2(gelu_exact(v0), gelu_exact(v1));
                    *reinterpret_cast<float2*>(hp + col) = st;
                }
            } else {
                float* yp = g_y + (size_t)(hoff + mrow) * D_DIM + n_base;
#pragma unroll
                for (int j = 0; j < 4; j++) {
                    int col = wn + j * 8 + tig * 2;
                    float v0 = c[i][j][half * 2 + 0] + be[col];
                    float v1 = c[i][j][half * 2 + 1] + be[col + 1];
                    float2 st = make_float2(v0, v1);
                    *reinterpret_cast<float2*>(yp + col) = st;
                }
            }
        }
    }
}

__global__ void ln_k(const float* __restrict__ x,
                     const float* __restrict__ gamma,
                     const float* __restrict__ beta,
                     float* __restrict__ out) {
    int t = blockIdx.x;
    int tid = threadIdx.x;
    int lane = tid & 31, wid = tid >> 5;

    int i0 = g_inv[t * 2 + 0], i1 = g_inv[t * 2 + 1];
    float gt0 = g_gate[i0], gt1 = g_gate[i1];
    size_t r0 = (size_t)(g_off[i0 >> 13] + (i0 & (CAP - 1)));
    size_t r1 = (size_t)(g_off[i1 >> 13] + (i1 & (CAP - 1)));
    const float* y0 = g_y + r0 * D_DIM;
    const float* y1 = g_y + r1 * D_DIM;
    const float* xr = x + (size_t)t * D_DIM;

    int c = tid * 4;
    float4 xv = *reinterpret_cast<const float4*>(xr + c);
    float4 av = *reinterpret_cast<const float4*>(y0 + c);
    float4 bv = *reinterpret_cast<const float4*>(y1 + c);
    float z0 = xv.x + gt0 * av.x + gt1 * bv.x;
    float z1 = xv.y + gt0 * av.y + gt1 * bv.y;
    float z2 = xv.z + gt0 * av.z + gt1 * bv.z;
    float z3 = xv.w + gt0 * av.w + gt1 * bv.w;

    float s  = z0 + z1 + z2 + z3;
    float sq = z0 * z0 + z1 * z1 + z2 * z2 + z3 * z3;
#pragma unroll
    for (int o = 16; o; o >>= 1) {
        s  += __shfl_xor_sync(0xffffffffu, s, o);
        sq += __shfl_xor_sync(0xffffffffu, sq, o);
    }
    __shared__ float ws[8], wq[8];
    if (lane == 0) { ws[wid] = s; wq[wid] = sq; }
    __syncthreads();
    if (wid == 0) {
        float s2 = (lane < 8) ? ws[lane] : 0.f;
        float q2 = (lane < 8) ? wq[lane] : 0.f;
#pragma unroll
        for (int o = 4; o; o >>= 1) {
            s2 += __shfl_xor_sync(0xffffffffu, s2, o);
            q2 += __shfl_xor_sync(0xffffffffu, q2, o);
        }
        if (lane == 0) { ws[0] = s2; wq[0] = q2; }
    }
    __syncthreads();
    float mu  = ws[0] * (1.0f / D_DIM);
    float var = wq[0] * (1.0f / D_DIM) - mu * mu;
    float inv = rsqrtf(var + 1e-5f);

    float4 gm = *reinterpret_cast<const float4*>(gamma + c);
    float4 bt = *reinterpret_cast<const float4*>(beta + c);
    float4 o;
    o.x = (z0 - mu) * inv * gm.x + bt.x;
    o.y = (z1 - mu) * inv * gm.y + bt.y;
    o.z = (z2 - mu) * inv * gm.z + bt.z;
    o.w = (z3 - mu) * inv * gm.w + bt.w;
    *reinterpret_cast<float4*>(out + (size_t)t * D_DIM + c) = o;
}

// ---------------- launch ----------------
extern "C" void kernel_launch(void* const* d_in, const int* in_sizes, int n_in,
                              void* d_out, int out_size) {
    (void)in_sizes; (void)n_in; (void)out_size;
    const float* x     = (const float*)d_in[0];
    const float* gW    = (const float*)d_in[1];
    const float* gb    = (const float*)d_in[2];
    const float* W1    = (const float*)d_in[3];
    const float* b1    = (const float*)d_in[4];
    const float* W2    = (const float*)d_in[5];
    const float* b2    = (const float*)d_in[6];
    const float* gamma = (const float*)d_in[7];
    const float* beta  = (const float*)d_in[8];
    float* out = (float*)d_out;

    reset_k<<<1, 32>>>();
    router_k<<<N_TOK / 8, 256>>>(x, gW, gb);
    tail_k<<<1, 1>>>(out + (size_t)N_TOK * D_DIM);
    gemm_k<0><<<dim3(H_DIM / BN, CAP / BM, E_NUM), 256>>>(x, W1, b1, D_DIM, H_DIM);
    gemm_k<1><<<dim3(D_DIM / BN, CAP / BM, E_NUM), 256>>>(nullptr, W2, b2, H_DIM, D_DIM);
    ln_k<<<N_TOK, 256>>>(x, gamma, beta, out);
}

// round 3
// speedup vs baseline: 1.6501x; 1.6501x over previous
#include <cuda_runtime.h>
#include <math.h>
#include <stdint.h>

#define D_DIM 1024
#define H_DIM 2048
#define E_NUM 8
#define CAP   8192
#define N_TOK 8192
#define BM 128
#define BN 128
#define BK 32

// smem stage geometry (floats)
#define A_STRIDE 36              // 32 + 4 pad  -> bank = (4g+tig), conflict-free
#define B_STRIDE 136             // 128 + 8 pad -> bank = (8tig+g), conflict-free
#define A_BYTES  (BM * A_STRIDE * 4)          // 18432
#define B_BYTES  (BK * B_STRIDE * 4)          // 17408
#define STAGE_BYTES (A_BYTES + B_BYTES)       // 35840
#define SMEM_TOTAL (512 + 3 * STAGE_BYTES)    // 108032

// ---------------- device scratch ----------------
__device__ int   g_cnt[E_NUM];
__device__ int   g_off[E_NUM];
__device__ int   g_tok[E_NUM * CAP];
__device__ float g_gate[E_NUM * CAP];
__device__ int   g_inv[N_TOK * 2];
__device__ float g_imp[E_NUM];
__device__ float g_ent;
__device__ float g_h[(size_t)N_TOK * 2 * H_DIM];
__device__ float g_y[(size_t)N_TOK * 2 * D_DIM];

// ---------------- helpers ----------------
__device__ __forceinline__ uint32_t smem_u32(const void* p) {
    uint32_t a;
    asm("{ .reg .u64 t; cvta.to.shared.u64 t, %1; cvt.u32.u64 %0, t; }" : "=r"(a) : "l"(p));
    return a;
}
#define CP16(dst, src) \
    asm volatile("cp.async.cg.shared.global [%0], [%1], 16;" :: "r"(dst), "l"(src))
#define CP_COMMIT()  asm volatile("cp.async.commit_group;" ::: "memory")
#define CP_WAIT(n)   asm volatile("cp.async.wait_group %0;" :: "n"(n) : "memory")

__device__ __forceinline__ void mma_tf32(float* c, const unsigned* a, const unsigned* b) {
    asm volatile(
        "mma.sync.aligned.m16n8k8.row.col.f32.tf32.tf32.f32 "
        "{%0,%1,%2,%3}, {%4,%5,%6,%7}, {%8,%9}, {%0,%1,%2,%3};\n"
        : "+f"(c[0]), "+f"(c[1]), "+f"(c[2]), "+f"(c[3])
        : "r"(a[0]), "r"(a[1]), "r"(a[2]), "r"(a[3]),
          "r"(b[0]), "r"(b[1]));
}
__device__ __forceinline__ float gelu_exact(float v) {
    return 0.5f * v * (1.0f + erff(v * 0.70710678118654752440f));
}

// ---------------- small kernels ----------------
__global__ void reset_k() {
    int t = threadIdx.x;
    if (t < E_NUM) { g_cnt[t] = 0; g_imp[t] = 0.0f; }
    if (t == 0)    g_ent = 0.0f;
}

__global__ void router_k(const float* __restrict__ x,
                         const float* __restrict__ gW,
                         const float* __restrict__ gb) {
    int token = (blockIdx.x * blockDim.x + threadIdx.x) >> 5;
    int lane  = threadIdx.x & 31;
    if (token >= N_TOK) return;
    const float* xr = x + (size_t)token * D_DIM;

    float acc[8] = {0.f,0.f,0.f,0.f,0.f,0.f,0.f,0.f};
    for (int d = lane; d < D_DIM; d += 32) {
        float xv = xr[d];
        const float4* w = reinterpret_cast<const float4*>(gW + (size_t)d * E_NUM);
        float4 w0 = w[0], w1 = w[1];
        acc[0] += xv * w0.x; acc[1] += xv * w0.y; acc[2] += xv * w0.z; acc[3] += xv * w0.w;
        acc[4] += xv * w1.x; acc[5] += xv * w1.y; acc[6] += xv * w1.z; acc[7] += xv * w1.w;
    }
#pragma unroll
    for (int e = 0; e < 8; e++)
#pragma unroll
        for (int o = 16; o; o >>= 1) acc[e] += __shfl_xor_sync(0xffffffffu, acc[e], o);
    if (lane) return;

    float lg[8];
#pragma unroll
    for (int e = 0; e < 8; e++) lg[e] = acc[e] + gb[e];
    float mx = lg[0];
#pragma unroll
    for (int e = 1; e < 8; e++) mx = fmaxf(mx, lg[e]);
    float p[8], Z = 0.f;
#pragma unroll
    for (int e = 0; e < 8; e++) { p[e] = expf(lg[e] - mx); Z += p[e]; }
    float ent = 0.f;
#pragma unroll
    for (int e = 0; e < 8; e++) {
        p[e] /= Z;
        ent -= p[e] * logf(p[e] + 1e-8f);
        atomicAdd(&g_imp[e], p[e]);
    }
    atomicAdd(&g_ent, ent);

    int e0 = 0;
#pragma unroll
    for (int e = 1; e < 8; e++) if (lg[e] > lg[e0]) e0 = e;
    int e1 = -1;
#pragma unroll
    for (int e = 0; e < 8; e++) if (e != e0 && (e1 < 0 || lg[e] > lg[e1])) e1 = e;

    float dlt = expf(lg[e1] - lg[e0]);
    float g0 = 1.0f / (1.0f + dlt);
    float g1 = dlt / (1.0f + dlt);

    int s0 = atomicAdd(&g_cnt[e0], 1);
    g_tok[e0 * CAP + s0] = token; g_gate[e0 * CAP + s0] = g0;
    int s1 = atomicAdd(&g_cnt[e1], 1);
    g_tok[e1 * CAP + s1] = token; g_gate[e1 * CAP + s1] = g1;
    g_inv[token * 2 + 0] = e0 * CAP + s0;
    g_inv[token * 2 + 1] = e1 * CAP + s1;
}

__global__ void tail_k(float* __restrict__ out_tail) {
    if (threadIdx.x != 0 || blockIdx.x != 0) return;
    int off = 0;
    float loadv[8], impv[8];
    for (int e = 0; e < 8; e++) { g_off[e] = off; off += g_cnt[e]; }
    for (int e = 0; e < 8; e++) {
        loadv[e] = (float)g_cnt[e] / (float)N_TOK;
        impv[e]  = g_imp[e] / (float)N_TOK;
    }
    float bal = 0.f, util = 0.f;
    for (int e = 0; e < 8; e++) bal += impv[e] * loadv[e];
    bal *= (float)E_NUM;
    for (int e = 0; e < 8; e++) util -= loadv[e] * logf(loadv[e] + 1e-8f);
    out_tail[0] = bal;
    out_tail[1] = g_ent / (float)N_TOK;
    out_tail[2] = util;
    for (int e = 0; e < 8; e++) out_tail[3 + e]  = loadv[e];
    for (int e = 0; e < 8; e++) out_tail[11 + e] = impv[e];
}

// ---------------- pipelined tf32 grouped GEMM ----------------
// MODE 0: A = gather(x) [K=1024], B = W1[e] ([k][n]), epilogue bias+gelu -> g_h
// MODE 1: A = g_h       [K=2048], B = W2[e] ([k][n]), epilogue bias      -> g_y
template <int MODE>
__global__ void __launch_bounds__(256, 2)
gemm_cp(const float* __restrict__ x, const float* __restrict__ Bsrc,
        const float* __restrict__ bias) {
    constexpr int Kdim  = (MODE == 0) ? D_DIM : H_DIM;
    constexpr int Ncols = (MODE == 0) ? H_DIM : D_DIM;
    constexpr int NS    = Kdim / BK;

    extern __shared__ char smem[];
    const int e = blockIdx.z;
    const int cnt = g_cnt[e];
    const int m_base = blockIdx.y * BM;
    if (m_base >= cnt) return;
    const int n_base = blockIdx.x * BN;
    const int hoff = g_off[e];

    const int tid = threadIdx.x, wid = tid >> 5, lane = tid & 31;
    const uint32_t sb = smem_u32(smem);
    float* sBias = (float*)smem;

    for (int i = tid; i < BN; i += 256)
        sBias[i] = bias[(size_t)e * Ncols + n_base + i];

    // ---- copy assignments ----
    // A: 128 rows x 128B; chunk: row = (tid>>3)+32i, kch = tid&7
    const int kch = tid & 7;
    const float* Abase = (MODE == 0) ? x : (const float*)g_h;
    const float* aptr[4];
    uint32_t adst[4];
#pragma unroll
    for (int i = 0; i < 4; i++) {
        int r = (tid >> 3) + 32 * i;
        int am = m_base + r;
        size_t row;
        if (MODE == 0) row = (size_t)g_tok[e * CAP + (am < cnt ? am : m_base)];
        else           row = (size_t)(hoff + (am < cnt ? am : m_base));
        aptr[i] = Abase + row * Kdim + kch * 4;
        adst[i] = sb + 512 + r * (A_STRIDE * 4) + kch * 16;
    }
    // B: 32 k-rows x 512B; chunk: k = (tid>>5)+8i, nch = tid&31
    const int nch = tid & 31;
    const float* Bexp = Bsrc + (size_t)e * Kdim * Ncols + n_base + nch * 4;
    uint32_t bdst[4];
#pragma unroll
    for (int i = 0; i < 4; i++) {
        int k = (tid >> 5) + 8 * i;
        bdst[i] = sb + 512 + A_BYTES + k * (B_STRIDE * 4) + nch * 16;
    }

    // ---- fragment indices ----
    const int g = lane >> 2, tig = lane & 3;
    const int wm = (wid & 1) * 64;
    const int wn = (wid >> 1) * 32;

    float c[4][4][4];
#pragma unroll
    for (int i = 0; i < 4; i++)
#pragma unroll
        for (int j = 0; j < 4; j++)
#pragma unroll
            for (int r = 0; r < 4; r++) c[i][j][r] = 0.f;

    // ---- pipeline ----
    auto issue = [&](int s) {
        if (s >= NS) return;
        const int kb = s * BK;
        const uint32_t soff = (uint32_t)((s % 3) * STAGE_BYTES);
        const int kr = tid >> 5;
#pragma unroll
        for (int i = 0; i < 4; i++)
            CP16(adst[i] + soff, aptr[i] + kb);
#pragma unroll
        for (int i = 0; i < 4; i++)
            CP16(bdst[i] + soff, Bexp + (size_t)(kb + kr + 8 * i) * Ncols);
        CP_COMMIT();
    };

    issue(0);
    issue(1);

    for (int s = 0; s < NS; s++) {
        if (s + 1 < NS) CP_WAIT(1);
        else            CP_WAIT(0);
        __syncthreads();
        issue(s + 2);

        const float* As = (const float*)(smem + 512 + (s % 3) * STAGE_BYTES);
        const float* Bs = (const float*)(smem + 512 + (s % 3) * STAGE_BYTES + A_BYTES);

#pragma unroll
        for (int ks = 0; ks < 4; ks++) {
            const int k0 = ks * 8;
            unsigned a[4][4], b[4][2];
#pragma unroll
            for (int i = 0; i < 4; i++) {
                int r = wm + i * 16 + g;
                a[i][0] = __float_as_uint(As[r * A_STRIDE + k0 + tig]);
                a[i][1] = __float_as_uint(As[(r + 8) * A_STRIDE + k0 + tig]);
                a[i][2] = __float_as_uint(As[r * A_STRIDE + k0 + tig + 4]);
                a[i][3] = __float_as_uint(As[(r + 8) * A_STRIDE + k0 + tig + 4]);
            }
#pragma unroll
            for (int j = 0; j < 4; j++) {
                int cc = wn + j * 8 + g;
                b[j][0] = __float_as_uint(Bs[(k0 + tig) * B_STRIDE + cc]);
                b[j][1] = __float_as_uint(Bs[(k0 + tig + 4) * B_STRIDE + cc]);
            }
#pragma unroll
            for (int i = 0; i < 4; i++)
#pragma unroll
                for (int j = 0; j < 4; j++) mma_tf32(c[i][j], a[i], b[j]);
        }
        __syncthreads();
    }

    // ---- epilogue ----
#pragma unroll
    for (int i = 0; i < 4; i++) {
#pragma unroll
        for (int half = 0; half < 2; half++) {
            int lr = wm + i * 16 + g + half * 8;
            int mrow = m_base + lr;
            if (mrow >= cnt) continue;
            if (MODE == 0) {
                float* hp = g_h + (size_t)(hoff + mrow) * H_DIM + n_base;
#pragma unroll
                for (int j = 0; j < 4; j++) {
                    int col = wn + j * 8 + tig * 2;
                    float v0 = c[i][j][half * 2 + 0] + sBias[col];
                    float v1 = c[i][j][half * 2 + 1] + sBias[col + 1];
                    float2 st = make_float2(gelu_exact(v0), gelu_exact(v1));
                    *reinterpret_cast<float2*>(hp + col) = st;
                }
            } else {
                float* yp = g_y + (size_t)(hoff + mrow) * D_DIM + n_base;
#pragma unroll
                for (int j = 0; j < 4; j++) {
                    int col = wn + j * 8 + tig * 2;
                    float v0 = c[i][j][half * 2 + 0] + sBias[col];
                    float v1 = c[i][j][half * 2 + 1] + sBias[col + 1];
                    float2 st = make_float2(v0, v1);
                    *reinterpret_cast<float2*>(yp + col) = st;
                }
            }
        }
    }
}

// ---------------- LayerNorm ----------------
__global__ void ln_k(const float* __restrict__ x,
                     const float* __restrict__ gamma,
                     const float* __restrict__ beta,
                     float* __restrict__ out) {
    int t = blockIdx.x;
    int tid = threadIdx.x;
    int lane = tid & 31, wid = tid >> 5;

    int i0 = g_inv[t * 2 + 0], i1 = g_inv[t * 2 + 1];
    float gt0 = g_gate[i0], gt1 = g_gate[i1];
    size_t r0 = (size_t)(g_off[i0 >> 13] + (i0 & (CAP - 1)));
    size_t r1 = (size_t)(g_off[i1 >> 13] + (i1 & (CAP - 1)));
    const float* y0 = g_y + r0 * D_DIM;
    const float* y1 = g_y + r1 * D_DIM;
    const float* xr = x + (size_t)t * D_DIM;

    int c = tid * 4;
    float4 xv = *reinterpret_cast<const float4*>(xr + c);
    float4 av = *reinterpret_cast<const float4*>(y0 + c);
    float4 bv = *reinterpret_cast<const float4*>(y1 + c);
    float z0 = xv.x + gt0 * av.x + gt1 * bv.x;
    float z1 = xv.y + gt0 * av.y + gt1 * bv.y;
    float z2 = xv.z + gt0 * av.z + gt1 * bv.z;
    float z3 = xv.w + gt0 * av.w + gt1 * bv.w;

    float s  = z0 + z1 + z2 + z3;
    float sq = z0 * z0 + z1 * z1 + z2 * z2 + z3 * z3;
#pragma unroll
    for (int o = 16; o; o >>= 1) {
        s  += __shfl_xor_sync(0xffffffffu, s, o);
        sq += __shfl_xor_sync(0xffffffffu, sq, o);
    }
    __shared__ float ws[8], wq[8];
    if (lane == 0) { ws[wid] = s; wq[wid] = sq; }
    __syncthreads();
    if (wid == 0) {
        float s2 = (lane < 8) ? ws[lane] : 0.f;
        float q2 = (lane < 8) ? wq[lane] : 0.f;
#pragma unroll
        for (int o = 4; o; o >>= 1) {
            s2 += __shfl_xor_sync(0xffffffffu, s2, o);
            q2 += __shfl_xor_sync(0xffffffffu, q2, o);
        }
        if (lane == 0) { ws[0] = s2; wq[0] = q2; }
    }
    __syncthreads();
    float mu  = ws[0] * (1.0f / D_DIM);
    float var = wq[0] * (1.0f / D_DIM) - mu * mu;
    float inv = rsqrtf(var + 1e-5f);

    float4 gm = *reinterpret_cast<const float4*>(gamma + c);
    float4 bt = *reinterpret_cast<const float4*>(beta + c);
    float4 o;
    o.x = (z0 - mu) * inv * gm.x + bt.x;
    o.y = (z1 - mu) * inv * gm.y + bt.y;
    o.z = (z2 - mu) * inv * gm.z + bt.z;
    o.w = (z3 - mu) * inv * gm.w + bt.w;
    *reinterpret_cast<float4*>(out + (size_t)t * D_DIM + c) = o;
}

// ---------------- launch ----------------
extern "C" void kernel_launch(void* const* d_in, const int* in_sizes, int n_in,
                              void* d_out, int out_size) {
    (void)in_sizes; (void)n_in; (void)out_size;
    const float* x     = (const float*)d_in[0];
    const float* gW    = (const float*)d_in[1];
    const float* gb    = (const float*)d_in[2];
    const float* W1    = (const float*)d_in[3];
    const float* b1    = (const float*)d_in[4];
    const float* W2    = (const float*)d_in[5];
    const float* b2    = (const float*)d_in[6];
    const float* gamma = (const float*)d_in[7];
    const float* beta  = (const float*)d_in[8];
    float* out = (float*)d_out;

    cudaFuncSetAttribute((const void*)gemm_cp<0>,
                         cudaFuncAttributeMaxDynamicSharedMemorySize, SMEM_TOTAL);
    cudaFuncSetAttribute((const void*)gemm_cp<1>,
                         cudaFuncAttributeMaxDynamicSharedMemorySize, SMEM_TOTAL);

    reset_k<<<1, 32>>>();
    router_k<<<N_TOK / 8, 256>>>(x, gW, gb);
    tail_k<<<1, 1>>>(out + (size_t)N_TOK * D_DIM);
    gemm_cp<0><<<dim3(H_DIM / BN, CAP / BM, E_NUM), 256, SMEM_TOTAL>>>(x, W1, b1);
    gemm_cp<1><<<dim3(D_DIM / BN, CAP / BM, E_NUM), 256, SMEM_TOTAL>>>(nullptr, W2, b2);
    ln_k<<<N_TOK, 256>>>(x, gamma, beta, out);
}

// round 4
// speedup vs baseline: 1.6922x; 1.0255x over previous
#include <cuda_runtime.h>
#include <math.h>
#include <stdint.h>

#define D_DIM 1024
#define H_DIM 2048
#define E_NUM 8
#define CAP   8192
#define N_TOK 8192
#define BM 128
#define BN 256
#define BK 32

#define A_BYTES 16384                    // 128 rows x 128B
#define B_BYTES 32768                    // 256 rows x 128B
#define STAGE_BYTES (A_BYTES + B_BYTES)  // 49152
#define NSTAGE 4
#define SMEM_TOTAL (1024 + NSTAGE * STAGE_BYTES)  // 197632

// ---------------- device scratch ----------------
__device__ int   g_cnt[E_NUM];
__device__ int   g_off[E_NUM];
__device__ int   g_tok[E_NUM * CAP];
__device__ float g_gate[E_NUM * CAP];
__device__ int   g_inv[N_TOK * 2];
__device__ float g_imp[E_NUM];
__device__ float g_ent;
__device__ float g_h[(size_t)N_TOK * 2 * H_DIM];
__device__ float g_y[(size_t)N_TOK * 2 * D_DIM];
__device__ float g_w1t[(size_t)E_NUM * H_DIM * D_DIM];  // [e][n=H][k=D]
__device__ float g_w2t[(size_t)E_NUM * D_DIM * H_DIM];  // [e][n=D][k=H]

// ---------------- helpers ----------------
__device__ __forceinline__ uint32_t smem_u32(const void* p) {
    uint32_t a;
    asm("{ .reg .u64 t; cvta.to.shared.u64 t, %1; cvt.u32.u64 %0, t; }" : "=r"(a) : "l"(p));
    return a;
}
#define CP16(dst, src) \
    asm volatile("cp.async.cg.shared.global [%0], [%1], 16;" :: "r"(dst), "l"(src))
#define CP_COMMIT()  asm volatile("cp.async.commit_group;" ::: "memory")
#define CP_WAIT(n)   asm volatile("cp.async.wait_group %0;" :: "n"(n) : "memory")

__device__ __forceinline__ void mma_tf32(float* c, unsigned a0, unsigned a1,
                                         unsigned a2, unsigned a3,
                                         unsigned b0, unsigned b1) {
    asm volatile(
        "mma.sync.aligned.m16n8k8.row.col.f32.tf32.tf32.f32 "
        "{%0,%1,%2,%3}, {%4,%5,%6,%7}, {%8,%9}, {%0,%1,%2,%3};\n"
        : "+f"(c[0]), "+f"(c[1]), "+f"(c[2]), "+f"(c[3])
        : "r"(a0), "r"(a1), "r"(a2), "r"(a3), "r"(b0), "r"(b1));
}
__device__ __forceinline__ float gelu_exact(float v) {
    return 0.5f * v * (1.0f + erff(v * 0.70710678118654752440f));
}

// ---------------- small kernels ----------------
__global__ void reset_k() {
    int t = threadIdx.x;
    if (t < E_NUM) { g_cnt[t] = 0; g_imp[t] = 0.0f; }
    if (t == 0)    g_ent = 0.0f;
}

__global__ void router_k(const float* __restrict__ x,
                         const float* __restrict__ gW,
                         const float* __restrict__ gb) {
    int token = (blockIdx.x * blockDim.x + threadIdx.x) >> 5;
    int lane  = threadIdx.x & 31;
    if (token >= N_TOK) return;
    const float* xr = x + (size_t)token * D_DIM;

    float acc[8] = {0.f,0.f,0.f,0.f,0.f,0.f,0.f,0.f};
    for (int d = lane; d < D_DIM; d += 32) {
        float xv = xr[d];
        const float4* w = reinterpret_cast<const float4*>(gW + (size_t)d * E_NUM);
        float4 w0 = w[0], w1 = w[1];
        acc[0] += xv * w0.x; acc[1] += xv * w0.y; acc[2] += xv * w0.z; acc[3] += xv * w0.w;
        acc[4] += xv * w1.x; acc[5] += xv * w1.y; acc[6] += xv * w1.z; acc[7] += xv * w1.w;
    }
#pragma unroll
    for (int e = 0; e < 8; e++)
#pragma unroll
        for (int o = 16; o; o >>= 1) acc[e] += __shfl_xor_sync(0xffffffffu, acc[e], o);
    if (lane) return;

    float lg[8];
#pragma unroll
    for (int e = 0; e < 8; e++) lg[e] = acc[e] + gb[e];
    float mx = lg[0];
#pragma unroll
    for (int e = 1; e < 8; e++) mx = fmaxf(mx, lg[e]);
    float p[8], Z = 0.f;
#pragma unroll
    for (int e = 0; e < 8; e++) { p[e] = expf(lg[e] - mx); Z += p[e]; }
    float ent = 0.f;
#pragma unroll
    for (int e = 0; e < 8; e++) {
        p[e] /= Z;
        ent -= p[e] * logf(p[e] + 1e-8f);
        atomicAdd(&g_imp[e], p[e]);
    }
    atomicAdd(&g_ent, ent);

    int e0 = 0;
#pragma unroll
    for (int e = 1; e < 8; e++) if (lg[e] > lg[e0]) e0 = e;
    int e1 = -1;
#pragma unroll
    for (int e = 0; e < 8; e++) if (e != e0 && (e1 < 0 || lg[e] > lg[e1])) e1 = e;

    float dlt = expf(lg[e1] - lg[e0]);
    float g0 = 1.0f / (1.0f + dlt);
    float g1 = dlt / (1.0f + dlt);

    int s0 = atomicAdd(&g_cnt[e0], 1);
    g_tok[e0 * CAP + s0] = token; g_gate[e0 * CAP + s0] = g0;
    int s1 = atomicAdd(&g_cnt[e1], 1);
    g_tok[e1 * CAP + s1] = token; g_gate[e1 * CAP + s1] = g1;
    g_inv[token * 2 + 0] = e0 * CAP + s0;
    g_inv[token * 2 + 1] = e1 * CAP + s1;
}

__global__ void tail_k(float* __restrict__ out_tail) {
    if (threadIdx.x != 0 || blockIdx.x != 0) return;
    int off = 0;
    float loadv[8], impv[8];
    for (int e = 0; e < 8; e++) { g_off[e] = off; off += g_cnt[e]; }
    for (int e = 0; e < 8; e++) {
        loadv[e] = (float)g_cnt[e] / (float)N_TOK;
        impv[e]  = g_imp[e] / (float)N_TOK;
    }
    float bal = 0.f, util = 0.f;
    for (int e = 0; e < 8; e++) bal += impv[e] * loadv[e];
    bal *= (float)E_NUM;
    for (int e = 0; e < 8; e++) util -= loadv[e] * logf(loadv[e] + 1e-8f);
    out_tail[0] = bal;
    out_tail[1] = g_ent / (float)N_TOK;
    out_tail[2] = util;
    for (int e = 0; e < 8; e++) out_tail[3 + e]  = loadv[e];
    for (int e = 0; e < 8; e++) out_tail[11 + e] = impv[e];
}

// W[e][k][n] -> WT[e][n][k]
__global__ void wtrans_k(const float* __restrict__ W, float* __restrict__ WT,
                         int K, int N) {
    __shared__ float t[32][33];
    int e = blockIdx.z, n0 = blockIdx.x * 32, k0 = blockIdx.y * 32;
    const float* Ws = W + (size_t)e * K * N;
    float* Wd = WT + (size_t)e * N * K;
    int tx = threadIdx.x & 31, ty = threadIdx.x >> 5;   // 256 threads: ty 0..7
#pragma unroll
    for (int i = 0; i < 4; i++)
        t[ty + 8 * i][tx] = Ws[(size_t)(k0 + ty + 8 * i) * N + n0 + tx];
    __syncthreads();
    int nl = threadIdx.x >> 3, kq = (threadIdx.x & 7) * 4;
    float4 o = make_float4(t[kq][nl], t[kq + 1][nl], t[kq + 2][nl], t[kq + 3][nl]);
    *reinterpret_cast<float4*>(Wd + (size_t)(n0 + nl) * K + k0 + kq) = o;
}

// ---------------- pipelined tf32 grouped GEMM (64x64 warp tiles) ----------------
// MODE 0: A = gather(x) [K=1024], B = g_w1t[e] ([n][k]), bias+gelu -> g_h
// MODE 1: A = g_h       [K=2048], B = g_w2t[e] ([n][k]), bias      -> g_y
template <int MODE>
__global__ void __launch_bounds__(256, 1)
gemm_cp(const float* __restrict__ x, const float* __restrict__ bias) {
    constexpr int Kdim  = (MODE == 0) ? D_DIM : H_DIM;
    constexpr int Ncols = (MODE == 0) ? H_DIM : D_DIM;
    constexpr int NS    = Kdim / BK;

    extern __shared__ char smem[];
    const int e = blockIdx.z;
    const int cnt = g_cnt[e];
    const int m_base = blockIdx.y * BM;
    if (m_base >= cnt) return;
    const int n_base = blockIdx.x * BN;
    const int hoff = g_off[e];

    const int tid = threadIdx.x, wid = tid >> 5, lane = tid & 31;
    const int g = lane >> 2, tig = lane & 3, g3 = g & 3;
    const int wm = (wid & 1) * 64;
    const int wn = (wid >> 1) * 64;
    const uint32_t sb = smem_u32(smem);
    float* sBias = (float*)smem;

    sBias[tid] = bias[(size_t)e * Ncols + n_base + tid];

    // ---- cp.async assignments ----
    const int cch = tid & 7;          // 16B chunk within a 128B row
    const int r0  = tid >> 3;         // base row 0..31 (rows r0 + 32i)
    const float* Wt = (MODE == 0) ? (const float*)g_w1t : (const float*)g_w2t;
    const float* Abase = (MODE == 0) ? x : (const float*)g_h;

    const float* aSrc[4];
#pragma unroll
    for (int i = 0; i < 4; i++) {
        int am = m_base + r0 + 32 * i;
        if (am >= cnt) am = cnt - 1;
        size_t row = (MODE == 0) ? (size_t)g_tok[e * CAP + am] : (size_t)(hoff + am);
        aSrc[i] = Abase + row * Kdim + cch * 4;
    }
    const float* bSrc = Wt + ((size_t)e * Ncols + n_base + r0) * Kdim + cch * 4;

    const uint32_t aDst0 = sb + 1024 + r0 * 128 + ((cch ^ (2 * (r0 & 3))) << 4);
    const uint32_t bDst0 = sb + 1024 + A_BYTES + r0 * 128 + ((cch ^ (2 * (r0 & 3))) << 4);

    float c[4][8][4];
#pragma unroll
    for (int i = 0; i < 4; i++)
#pragma unroll
        for (int j = 0; j < 8; j++)
#pragma unroll
            for (int r = 0; r < 4; r++) c[i][j][r] = 0.f;

    auto issue = [&](int s) {
        if (s < NS) {
            const int kb = s * BK;
            const uint32_t so = (uint32_t)((s & (NSTAGE - 1)) * STAGE_BYTES);
#pragma unroll
            for (int i = 0; i < 4; i++)
                CP16(aDst0 + so + i * 4096, aSrc[i] + kb);
#pragma unroll
            for (int i = 0; i < 8; i++)
                CP16(bDst0 + so + i * 4096, bSrc + (size_t)(32 * i) * Kdim + kb);
        }
        CP_COMMIT();
    };

    issue(0); issue(1); issue(2);

    // fragment base offsets (bytes within stage)
    const int aFrag = (wm + g) * 128 + 8 * tig;
    const int bFrag = A_BYTES + (wn + g) * 128 + 8 * tig;

    for (int s = 0; s < NS; s++) {
        CP_WAIT(2);
        __syncthreads();
        issue(s + 3);

        const char* stg = smem + 1024 + (s & (NSTAGE - 1)) * STAGE_BYTES;
#pragma unroll
        for (int ks = 0; ks < 4; ks++) {
            const int kx = 32 * (ks ^ g3);
            float2 aa0[4], aa1[4], bb[8];
#pragma unroll
            for (int i = 0; i < 4; i++) {
                aa0[i] = *(const float2*)(stg + aFrag + i * 2048 + kx);
                aa1[i] = *(const float2*)(stg + aFrag + i * 2048 + 1024 + kx);
            }
#pragma unroll
            for (int j = 0; j < 8; j++)
                bb[j] = *(const float2*)(stg + bFrag + j * 1024 + kx);
#pragma unroll
            for (int i = 0; i < 4; i++) {
                unsigned a0 = __float_as_uint(aa0[i].x), a1 = __float_as_uint(aa1[i].x);
                unsigned a2 = __float_as_uint(aa0[i].y), a3 = __float_as_uint(aa1[i].y);
#pragma unroll
                for (int j = 0; j < 8; j++)
                    mma_tf32(c[i][j], a0, a1, a2, a3,
                             __float_as_uint(bb[j].x), __float_as_uint(bb[j].y));
            }
        }
    }

    // ---- epilogue ----
#pragma unroll
    for (int i = 0; i < 4; i++) {
#pragma unroll
        for (int half = 0; half < 2; half++) {
            int mrow = m_base + wm + 16 * i + g + half * 8;
            if (mrow >= cnt) continue;
            if (MODE == 0) {
                float* hp = g_h + (size_t)(hoff + mrow) * H_DIM + n_base;
#pragma unroll
                for (int j = 0; j < 8; j++) {
                    int col = wn + j * 8 + tig * 2;
                    float v0 = c[i][j][half * 2 + 0] + sBias[col];
                    float v1 = c[i][j][half * 2 + 1] + sBias[col + 1];
                    *reinterpret_cast<float2*>(hp + col) =
                        make_float2(gelu_exact(v0), gelu_exact(v1));
                }
            } else {
                float* yp = g_y + (size_t)(hoff + mrow) * D_DIM + n_base;
#pragma unroll
                for (int j = 0; j < 8; j++) {
                    int col = wn + j * 8 + tig * 2;
                    float v0 = c[i][j][half * 2 + 0] + sBias[col];
                    float v1 = c[i][j][half * 2 + 1] + sBias[col + 1];
                    *reinterpret_cast<float2*>(yp + col) = make_float2(v0, v1);
                }
            }
        }
    }
}

// ---------------- LayerNorm ----------------
__global__ void ln_k(const float* __restrict__ x,
                     const float* __restrict__ gamma,
                     const float* __restrict__ beta,
                     float* __restrict__ out) {
    int t = blockIdx.x;
    int tid = threadIdx.x;
    int lane = tid & 31, wid = tid >> 5;

    int i0 = g_inv[t * 2 + 0], i1 = g_inv[t * 2 + 1];
    float gt0 = g_gate[i0], gt1 = g_gate[i1];
    size_t r0 = (size_t)(g_off[i0 >> 13] + (i0 & (CAP - 1)));
    size_t r1 = (size_t)(g_off[i1 >> 13] + (i1 & (CAP - 1)));
    const float* y0 = g_y + r0 * D_DIM;
    const float* y1 = g_y + r1 * D_DIM;
    const float* xr = x + (size_t)t * D_DIM;

    int c = tid * 4;
    float4 xv = *reinterpret_cast<const float4*>(xr + c);
    float4 av = *reinterpret_cast<const float4*>(y0 + c);
    float4 bv = *reinterpret_cast<const float4*>(y1 + c);
    float z0 = xv.x + gt0 * av.x + gt1 * bv.x;
    float z1 = xv.y + gt0 * av.y + gt1 * bv.y;
    float z2 = xv.z + gt0 * av.z + gt1 * bv.z;
    float z3 = xv.w + gt0 * av.w + gt1 * bv.w;

    float s  = z0 + z1 + z2 + z3;
    float sq = z0 * z0 + z1 * z1 + z2 * z2 + z3 * z3;
#pragma unroll
    for (int o = 16; o; o >>= 1) {
        s  += __shfl_xor_sync(0xffffffffu, s, o);
        sq += __shfl_xor_sync(0xffffffffu, sq, o);
    }
    __shared__ float ws[8], wq[8];
    if (lane == 0) { ws[wid] = s; wq[wid] = sq; }
    __syncthreads();
    if (wid == 0) {
        float s2 = (lane < 8) ? ws[lane] : 0.f;
        float q2 = (lane < 8) ? wq[lane] : 0.f;
#pragma unroll
        for (int o = 4; o; o >>= 1) {
            s2 += __shfl_xor_sync(0xffffffffu, s2, o);
            q2 += __shfl_xor_sync(0xffffffffu, q2, o);
        }
        if (lane == 0) { ws[0] = s2; wq[0] = q2; }
    }
    __syncthreads();
    float mu  = ws[0] * (1.0f / D_DIM);
    float var = wq[0] * (1.0f / D_DIM) - mu * mu;
    float inv = rsqrtf(var + 1e-5f);

    float4 gm = *reinterpret_cast<const float4*>(gamma + c);
    float4 bt = *reinterpret_cast<const float4*>(beta + c);
    float4 o;
    o.x = (z0 - mu) * inv * gm.x + bt.x;
    o.y = (z1 - mu) * inv * gm.y + bt.y;
    o.z = (z2 - mu) * inv * gm.z + bt.z;
    o.w = (z3 - mu) * inv * gm.w + bt.w;
    *reinterpret_cast<float4*>(out + (size_t)t * D_DIM + c) = o;
}

// ---------------- launch ----------------
extern "C" void kernel_launch(void* const* d_in, const int* in_sizes, int n_in,
                              void* d_out, int out_size) {
    (void)in_sizes; (void)n_in; (void)out_size;
    const float* x     = (const float*)d_in[0];
    const float* gW    = (const float*)d_in[1];
    const float* gb    = (const float*)d_in[2];
    const float* W1    = (const float*)d_in[3];
    const float* b1    = (const float*)d_in[4];
    const float* W2    = (const float*)d_in[5];
    const float* b2    = (const float*)d_in[6];
    const float* gamma = (const float*)d_in[7];
    const float* beta  = (const float*)d_in[8];
    float* out = (float*)d_out;

    cudaFuncSetAttribute((const void*)gemm_cp<0>,
                         cudaFuncAttributeMaxDynamicSharedMemorySize, SMEM_TOTAL);
    cudaFuncSetAttribute((const void*)gemm_cp<1>,
                         cudaFuncAttributeMaxDynamicSharedMemorySize, SMEM_TOTAL);

    float* w1t; cudaGetSymbolAddress((void**)&w1t, g_w1t);
    float* w2t; cudaGetSymbolAddress((void**)&w2t, g_w2t);

    reset_k<<<1, 32>>>();
    router_k<<<N_TOK / 8, 256>>>(x, gW, gb);
    tail_k<<<1, 1>>>(out + (size_t)N_TOK * D_DIM);
    wtrans_k<<<dim3(H_DIM / 32, D_DIM / 32, E_NUM), 256>>>(W1, w1t, D_DIM, H_DIM);
    wtrans_k<<<dim3(D_DIM / 32, H_DIM / 32, E_NUM), 256>>>(W2, w2t, H_DIM, D_DIM);
    gemm_cp<0><<<dim3(H_DIM / BN, CAP / BM, E_NUM), 256, SMEM_TOTAL>>>(x, b1);
    gemm_cp<1><<<dim3(D_DIM / BN, CAP / BM, E_NUM), 256, SMEM_TOTAL>>>(nullptr, b2);
    ln_k<<<N_TOK, 256>>>(x, gamma, beta, out);
}